// round 2
// baseline (speedup 1.0000x reference)
#include <cuda_runtime.h>
#include <math.h>

#define BDIM   256
#define DD     64
#define OO     32
#define KMIX   15
#define HIDN   60
#define PITCH  68
#define SPITCH 36
#define LOG2PI 1.8378770664093453f

// smem layout (floats)
#define OFF_P    0
#define OFF_FT   (OFF_P   + DD*PITCH)      // 4352, dead after GEMM2 -> union {S, recip, Z}
#define OFF_T    (OFF_FT  + DD*PITCH)      // 8704, dead after GEMM2 -> union {HP}
#define OFF_HW   (OFF_T   + DD*PITCH)      // 13056
#define OFF_M    (OFF_HW  + OO*PITCH)      // 15232
#define OFF_PM   (OFF_M   + DD)
#define OFF_INN  (OFF_PM  + DD)
#define OFF_H    (OFF_INN + OO)
#define OFF_W    (OFF_H   + DD)
#define OFF_WV   (OFF_W   + 16)
#define OFF_RED  (OFF_WV  + OO)
#define SMEM_FLOATS (OFF_RED + 4)
// unions
#define OFF_S     OFF_FT
#define OFF_RECIP (OFF_FT + OO*SPITCH)          // 1152
#define OFF_Z     (OFF_FT + OO*SPITCH + 32)     // 1184 (16B aligned)
#define OFF_HP    OFF_T

__device__ __forceinline__ float4 ld4(const float* p){ return *reinterpret_cast<const float4*>(p); }
__device__ __forceinline__ void   st4(float* p, float4 v){ *reinterpret_cast<float4*>(p) = v; }
__device__ __forceinline__ float4 fma4(float a, float4 b, float4 c){
    c.x = fmaf(a,b.x,c.x); c.y = fmaf(a,b.y,c.y);
    c.z = fmaf(a,b.z,c.z); c.w = fmaf(a,b.w,c.w);
    return c;
}
__device__ __forceinline__ float dot4acc(float4 a, float4 b, float c){
    c = fmaf(a.x,b.x,c); c = fmaf(a.y,b.y,c);
    c = fmaf(a.z,b.z,c); c = fmaf(a.w,b.w,c);
    return c;
}

__global__ __launch_bounds__(BDIM, 3)
void rkn_kernel(const float* __restrict__ g_mean,
                const float* __restrict__ g_cov,
                const float* __restrict__ g_obs,
                const float* __restrict__ g_w1,
                const float* __restrict__ g_b1,
                const float* __restrict__ g_w2,
                const float* __restrict__ g_b2,
                const float* __restrict__ g_basis,
                const float* __restrict__ g_pnf,
                const float* __restrict__ g_pnd,
                const float* __restrict__ g_onf,
                const float* __restrict__ g_ond,
                const float* __restrict__ g_Hw,
                const float* __restrict__ g_Hb,
                float* __restrict__ o_mean,
                float* __restrict__ o_cov,
                float* __restrict__ o_ll)
{
    extern __shared__ float smem[];
    float* sP    = smem + OFF_P;
    float* sFt   = smem + OFF_FT;
    float* sT    = smem + OFF_T;
    float* sHw   = smem + OFF_HW;
    float* sHP   = smem + OFF_HP;    // union over sT
    float* sS    = smem + OFF_S;     // union over sFt
    float* sRcp  = smem + OFF_RECIP;
    float* sZ    = smem + OFF_Z;
    float* sm_   = smem + OFF_M;
    float* spm   = smem + OFF_PM;
    float* sinn  = smem + OFF_INN;
    float* sh    = smem + OFF_H;
    float* sw    = smem + OFF_W;
    float* sWv   = smem + OFF_WV;
    float* sred  = smem + OFF_RED;

    const int b   = blockIdx.x;
    const int tid = threadIdx.x;
    const int tx  = tid & 15;
    const int ty  = tid >> 4;

    // ---------------- loads ----------------
    if (tid < DD) sm_[tid] = g_mean[b*DD + tid];
    {   // Hw: 2048 floats
        int base = tid * 8;
        int r = base >> 6, c = base & 63;
        st4(sHw + r*PITCH + c,     ld4(g_Hw + base));
        st4(sHw + r*PITCH + c + 4, ld4(g_Hw + base + 4));
    }
    {   // P: 4096 floats
        const float* Pg = g_cov + (size_t)b*DD*DD;
        int base = tid*16;
        #pragma unroll
        for (int q=0;q<4;q++){
            int g = base + q*4;
            st4(sP + (g>>6)*PITCH + (g&63), ld4(Pg + g));
        }
    }
    __syncthreads();

    // ---------------- MLP layer 1 ----------------
    if (tid < HIDN) {
        float acc = g_b1[tid];
        const float* w1r = g_w1 + tid*DD;
        #pragma unroll 16
        for (int d=0; d<DD; d++) acc = fmaf(w1r[d], sm_[d], acc);
        sh[tid] = acc > 0.f ? acc : expm1f(acc);   // elu
    }
    __syncthreads();

    // ---------------- MLP layer 2 + softmax (fused, warp 0 lanes 0..15) ----------------
    if (tid < 16) {
        float acc = -1e30f;
        if (tid < KMIX) {
            acc = g_b2[tid];
            const float* w2r = g_w2 + tid*HIDN;
            #pragma unroll 15
            for (int j=0;j<HIDN;j++) acc = fmaf(w2r[j], sh[j], acc);
        }
        float mx = acc;
        #pragma unroll
        for (int off=8;off;off>>=1) mx = fmaxf(mx, __shfl_xor_sync(0xFFFFu, mx, off));
        float e = expf(acc - mx);                  // lane15 -> 0
        float s = e;
        #pragma unroll
        for (int off=8;off;off>>=1) s += __shfl_xor_sync(0xFFFFu, s, off);
        if (tid < KMIX) sw[tid] = e / s;
    }
    __syncthreads();

    // ---------------- F = sum_k w_k basis_k (stored transposed) ----------------
    {
        float wl[KMIX];
        #pragma unroll
        for (int k=0;k<KMIX;k++) wl[k] = sw[k];
        int base = tid*16;
        int r = base >> 6;
        #pragma unroll
        for (int q=0;q<4;q++){
            int g = base + q*4;
            float4 acc = make_float4(0.f,0.f,0.f,0.f);
            #pragma unroll
            for (int k=0;k<KMIX;k++){
                float4 v = ld4(g_basis + k*4096 + g);
                acc = fma4(wl[k], v, acc);
            }
            int c = g & 63;
            sFt[(c+0)*PITCH + r] = acc.x;
            sFt[(c+1)*PITCH + r] = acc.y;
            sFt[(c+2)*PITCH + r] = acc.z;
            sFt[(c+3)*PITCH + r] = acc.w;
        }
    }
    __syncthreads();

    // pred_mean = F @ m
    if (tid < DD) {
        float acc = 0.f;
        #pragma unroll 16
        for (int k=0;k<DD;k++) acc = fmaf(sFt[k*PITCH + tid], sm_[k], acc);
        spm[tid] = acc;
    }

    // ---------------- GEMM1: T = F @ P ----------------
    {
        const int r0 = ty*4, c0 = tx*4;
        float4 acc0=make_float4(0,0,0,0), acc1=acc0, acc2=acc0, acc3=acc0;
        for (int k=0;k<DD;k+=4){
            float4 a0 = ld4(sFt + (k+0)*PITCH + r0);
            float4 a1 = ld4(sFt + (k+1)*PITCH + r0);
            float4 a2 = ld4(sFt + (k+2)*PITCH + r0);
            float4 a3 = ld4(sFt + (k+3)*PITCH + r0);
            float4 p0 = ld4(sP + (k+0)*PITCH + c0);
            acc0=fma4(a0.x,p0,acc0); acc1=fma4(a0.y,p0,acc1); acc2=fma4(a0.z,p0,acc2); acc3=fma4(a0.w,p0,acc3);
            float4 p1 = ld4(sP + (k+1)*PITCH + c0);
            acc0=fma4(a1.x,p1,acc0); acc1=fma4(a1.y,p1,acc1); acc2=fma4(a1.z,p1,acc2); acc3=fma4(a1.w,p1,acc3);
            float4 p2 = ld4(sP + (k+2)*PITCH + c0);
            acc0=fma4(a2.x,p2,acc0); acc1=fma4(a2.y,p2,acc1); acc2=fma4(a2.z,p2,acc2); acc3=fma4(a2.w,p2,acc3);
            float4 p3 = ld4(sP + (k+3)*PITCH + c0);
            acc0=fma4(a3.x,p3,acc0); acc1=fma4(a3.y,p3,acc1); acc2=fma4(a3.z,p3,acc2); acc3=fma4(a3.w,p3,acc3);
        }
        st4(sT + (r0+0)*PITCH + c0, acc0);
        st4(sT + (r0+1)*PITCH + c0, acc1);
        st4(sT + (r0+2)*PITCH + c0, acc2);
        st4(sT + (r0+3)*PITCH + c0, acc3);
    }
    __syncthreads();

    // innovation
    if (tid < OO) {
        float acc = g_Hb[tid];
        #pragma unroll 8
        for (int k=0;k<DD;k++) acc = fmaf(sHw[tid*PITCH+k], spm[k], acc);
        sinn[tid] = g_obs[b*OO + tid] - acc;
    }

    // ---------------- GEMM2: pred_cov = T @ F^T + Q (into sP, in place) ----------------
    {
        const int r0 = ty*4, c0 = tx*4;
        float4 acc0=make_float4(0,0,0,0), acc1=acc0, acc2=acc0, acc3=acc0;
        for (int k=0;k<DD;k+=4){
            float4 t0 = ld4(sT + (r0+0)*PITCH + k);
            float4 t1 = ld4(sT + (r0+1)*PITCH + k);
            float4 t2 = ld4(sT + (r0+2)*PITCH + k);
            float4 t3 = ld4(sT + (r0+3)*PITCH + k);
            float4 f0 = ld4(sFt + (k+0)*PITCH + c0);
            acc0=fma4(t0.x,f0,acc0); acc1=fma4(t1.x,f0,acc1); acc2=fma4(t2.x,f0,acc2); acc3=fma4(t3.x,f0,acc3);
            float4 f1 = ld4(sFt + (k+1)*PITCH + c0);
            acc0=fma4(t0.y,f1,acc0); acc1=fma4(t1.y,f1,acc1); acc2=fma4(t2.y,f1,acc2); acc3=fma4(t3.y,f1,acc3);
            float4 f2 = ld4(sFt + (k+2)*PITCH + c0);
            acc0=fma4(t0.z,f2,acc0); acc1=fma4(t1.z,f2,acc1); acc2=fma4(t2.z,f2,acc2); acc3=fma4(t3.z,f2,acc3);
            float4 f3 = ld4(sFt + (k+3)*PITCH + c0);
            acc0=fma4(t0.w,f3,acc0); acc1=fma4(t1.w,f3,acc1); acc2=fma4(t2.w,f3,acc2); acc3=fma4(t3.w,f3,acc3);
        }
        float pa[4][3], pb[4][3];
        #pragma unroll
        for (int i=0;i<4;i++)
            #pragma unroll
            for (int r=0;r<3;r++){
                pa[i][r] = g_pnf[(r0+i)*3 + r];
                pb[i][r] = g_pnf[(c0+i)*3 + r];
            }
        float* accp[4] = { &acc0.x, &acc1.x, &acc2.x, &acc3.x };
        #pragma unroll
        for (int i=0;i<4;i++){
            #pragma unroll
            for (int j=0;j<4;j++){
                float q = pa[i][0]*pb[j][0];
                q = fmaf(pa[i][1], pb[j][1], q);
                q = fmaf(pa[i][2], pb[j][2], q);
                accp[i][j] += q;
            }
        }
        if (r0 == c0){
            #pragma unroll
            for (int i=0;i<4;i++) accp[i][i] += expf(g_pnd[r0+i]);
        }
        st4(sP + (r0+0)*PITCH + c0, acc0);
        st4(sP + (r0+1)*PITCH + c0, acc1);
        st4(sP + (r0+2)*PITCH + c0, acc2);
        st4(sP + (r0+3)*PITCH + c0, acc3);
    }
    __syncthreads();

    // ---------------- HP = Hw @ pred_cov  [32][64]  (into old sT space) ----------------
    {
        const int o0 = ty*2, c0 = tx*4;
        float4 accA = make_float4(0,0,0,0), accB = accA;
        for (int k=0;k<DD;k+=4){
            float4 h0 = ld4(sHw + (o0+0)*PITCH + k);
            float4 h1 = ld4(sHw + (o0+1)*PITCH + k);
            float4 p0 = ld4(sP + (k+0)*PITCH + c0);
            accA=fma4(h0.x,p0,accA); accB=fma4(h1.x,p0,accB);
            float4 p1 = ld4(sP + (k+1)*PITCH + c0);
            accA=fma4(h0.y,p1,accA); accB=fma4(h1.y,p1,accB);
            float4 p2 = ld4(sP + (k+2)*PITCH + c0);
            accA=fma4(h0.z,p2,accA); accB=fma4(h1.z,p2,accB);
            float4 p3 = ld4(sP + (k+3)*PITCH + c0);
            accA=fma4(h0.w,p3,accA); accB=fma4(h1.w,p3,accB);
        }
        st4(sHP + (o0+0)*PITCH + c0, accA);
        st4(sHP + (o0+1)*PITCH + c0, accB);
    }
    __syncthreads();

    // ---------------- S = HP @ Hw^T + Rn  (into old sFt space) ----------------
    {
        const int o0 = ty*2, p0 = tx*2;
        float a00=0.f,a01=0.f,a10=0.f,a11=0.f;
        for (int k=0;k<DD;k+=4){
            float4 x0 = ld4(sHP + (o0+0)*PITCH + k);
            float4 x1 = ld4(sHP + (o0+1)*PITCH + k);
            float4 y0 = ld4(sHw + (p0+0)*PITCH + k);
            float4 y1 = ld4(sHw + (p0+1)*PITCH + k);
            a00 = dot4acc(x0,y0,a00); a01 = dot4acc(x0,y1,a01);
            a10 = dot4acc(x1,y0,a10); a11 = dot4acc(x1,y1,a11);
        }
        float oa[2][3], ob[2][3];
        #pragma unroll
        for (int i=0;i<2;i++)
            #pragma unroll
            for (int r=0;r<3;r++){
                oa[i][r] = g_onf[(o0+i)*3 + r];
                ob[i][r] = g_onf[(p0+i)*3 + r];
            }
        a00 += oa[0][0]*ob[0][0] + oa[0][1]*ob[0][1] + oa[0][2]*ob[0][2];
        a01 += oa[0][0]*ob[1][0] + oa[0][1]*ob[1][1] + oa[0][2]*ob[1][2];
        a10 += oa[1][0]*ob[0][0] + oa[1][1]*ob[0][1] + oa[1][2]*ob[0][2];
        a11 += oa[1][0]*ob[1][0] + oa[1][1]*ob[1][1] + oa[1][2]*ob[1][2];
        if (o0 == p0){
            a00 += expf(g_ond[o0+0]);
            a11 += expf(g_ond[o0+1]);
        }
        sS[(o0+0)*SPITCH + p0+0] = a00;
        sS[(o0+0)*SPITCH + p0+1] = a01;
        sS[(o0+1)*SPITCH + p0+0] = a10;
        sS[(o0+1)*SPITCH + p0+1] = a11;
    }
    __syncthreads();

    // ---------------- Cholesky (in place) + log_det + recip diag : warp 0 ----------------
    if (tid < 32) {
        const int i = tid;
        for (int j=0;j<32;j++){
            float s = 0.f;
            if (i >= j){
                s = sS[i*SPITCH + j];
                for (int k=0;k<j;k++) s = fmaf(-sS[i*SPITCH+k], sS[j*SPITCH+k], s);
            }
            float dj  = __shfl_sync(0xffffffffu, s, j);
            float ljj = sqrtf(dj);
            if (i == j)      sS[i*SPITCH+j] = ljj;
            else if (i > j)  sS[i*SPITCH+j] = s / ljj;
            __syncwarp();
        }
        float di = sS[i*SPITCH+i];
        sRcp[i] = 1.0f / di;
        float ld = logf(di);
        #pragma unroll
        for (int off=16;off;off>>=1) ld += __shfl_xor_sync(0xffffffffu, ld, off);
        if (i == 0) sred[0] = 2.f*ld;
    }
    __syncthreads();

    // ---------------- Triangular solves:  S * [Z | w] = [HP | inn] ----------------
    // tid 0..63: column tid of Z (Z = S^{-1} HP, i.e. Z = Kg^T)
    // tid 64   : w = S^{-1} inn ; quad = ||L^{-1} inn||^2
    if (tid < 65) {
        float y[OO];
        if (tid < 64) {
            #pragma unroll
            for (int o=0;o<OO;o++) y[o] = sHP[o*PITCH + tid];
        } else {
            #pragma unroll
            for (int o=0;o<OO;o++) y[o] = sinn[o];
        }
        // forward: L y = rhs
        #pragma unroll
        for (int r=0;r<OO;r++){
            float acc = y[r];
            #pragma unroll
            for (int k=0;k<r;k++) acc = fmaf(-sS[r*SPITCH+k], y[k], acc);
            y[r] = acc * sRcp[r];
        }
        float quad = 0.f;
        if (tid == 64){
            #pragma unroll
            for (int o=0;o<OO;o++) quad = fmaf(y[o], y[o], quad);
        }
        // backward: L^T x = y
        #pragma unroll
        for (int r=OO-1;r>=0;r--){
            float acc = y[r];
            #pragma unroll
            for (int k=r+1;k<OO;k++) acc = fmaf(-sS[k*SPITCH+r], y[k], acc);
            y[r] = acc * sRcp[r];
        }
        if (tid < 64) {
            #pragma unroll
            for (int o=0;o<OO;o++) sZ[o*PITCH + tid] = y[o];
        } else {
            #pragma unroll
            for (int o=0;o<OO;o++) sWv[o] = y[o];
            sred[1] = quad;
        }
    }
    __syncthreads();

    // ---------------- outputs ----------------
    if (tid < DD) {           // post_mean = pred_mean + (HP)^T w
        float acc = spm[tid];
        #pragma unroll 8
        for (int o=0;o<OO;o++) acc = fmaf(sHP[o*PITCH+tid], sWv[o], acc);
        o_mean[(size_t)b*DD + tid] = acc;
    }
    if (tid == 64) {
        o_ll[b] = -0.5f*(sred[0] + sred[1] + 32.f*LOG2PI);
    }

    // post_cov = pred_cov - (HP)^T Z
    {
        const int r0 = ty*4, c0 = tx*4;
        float4 acc0=make_float4(0,0,0,0), acc1=acc0, acc2=acc0, acc3=acc0;
        #pragma unroll 4
        for (int o=0;o<OO;o++){
            float4 a = ld4(sHP + o*PITCH + r0);
            float4 z = ld4(sZ  + o*PITCH + c0);
            acc0 = fma4(a.x, z, acc0);
            acc1 = fma4(a.y, z, acc1);
            acc2 = fma4(a.z, z, acc2);
            acc3 = fma4(a.w, z, acc3);
        }
        float* outr = o_cov + (size_t)b*4096;
        float4 accs[4] = {acc0, acc1, acc2, acc3};
        #pragma unroll
        for (int i=0;i<4;i++){
            float4 pc = ld4(sP + (r0+i)*PITCH + c0);
            float4 res = make_float4(pc.x - accs[i].x, pc.y - accs[i].y,
                                     pc.z - accs[i].z, pc.w - accs[i].w);
            st4(outr + (r0+i)*64 + c0, res);
        }
    }
}

extern "C" void kernel_launch(void* const* d_in, const int* in_sizes, int n_in,
                              void* d_out, int out_size)
{
    const float* g_mean  = (const float*)d_in[0];
    const float* g_cov   = (const float*)d_in[1];
    const float* g_obs   = (const float*)d_in[2];
    const float* g_w1    = (const float*)d_in[3];
    const float* g_b1    = (const float*)d_in[4];
    const float* g_w2    = (const float*)d_in[5];
    const float* g_b2    = (const float*)d_in[6];
    const float* g_basis = (const float*)d_in[7];
    const float* g_pnf   = (const float*)d_in[8];
    const float* g_pnd   = (const float*)d_in[9];
    const float* g_onf   = (const float*)d_in[10];
    const float* g_ond   = (const float*)d_in[11];
    const float* g_Hw    = (const float*)d_in[12];
    const float* g_Hb    = (const float*)d_in[13];

    const int B = in_sizes[0] / DD;
    float* out    = (float*)d_out;
    float* o_mean = out;
    float* o_cov  = out + (size_t)B*DD;
    float* o_ll   = out + (size_t)B*DD + (size_t)B*DD*DD;

    const int smem_bytes = SMEM_FLOATS * (int)sizeof(float);
    cudaFuncSetAttribute(rkn_kernel, cudaFuncAttributeMaxDynamicSharedMemorySize, smem_bytes);
    rkn_kernel<<<B, BDIM, smem_bytes>>>(g_mean, g_cov, g_obs, g_w1, g_b1, g_w2, g_b2,
                                        g_basis, g_pnf, g_pnd, g_onf, g_ond, g_Hw, g_Hb,
                                        o_mean, o_cov, o_ll);
}

// round 3
// speedup vs baseline: 1.0466x; 1.0466x over previous
#include <cuda_runtime.h>
#include <math.h>

#define BDIM   256
#define DD     64
#define OO     32
#define KMIX   15
#define HIDN   60
#define PITCH  68
#define SPITCH 36
#define LOG2PI 1.8378770664093453f

// smem layout (floats)
#define OFF_P    0
#define OFF_FT   (OFF_P   + DD*PITCH)      // dead after GEMM2 -> union {S, recip, Z}
#define OFF_T    (OFF_FT  + DD*PITCH)      // dead after GEMM2 -> union {HP}
#define OFF_HW   (OFF_T   + DD*PITCH)
#define OFF_M    (OFF_HW  + OO*PITCH)
#define OFF_PM   (OFF_M   + DD)
#define OFF_INN  (OFF_PM  + DD)
#define OFF_H    (OFF_INN + OO)
#define OFF_W    (OFF_H   + DD)
#define OFF_WV   (OFF_W   + 16)
#define OFF_RED  (OFF_WV  + OO)
#define SMEM_FLOATS (OFF_RED + 4)
// unions
#define OFF_S     OFF_FT
#define OFF_RECIP (OFF_FT + OO*SPITCH)
#define OFF_Z     (OFF_FT + OO*SPITCH + 32)
#define OFF_HP    OFF_T

__device__ __forceinline__ float4 ld4(const float* p){ return *reinterpret_cast<const float4*>(p); }
__device__ __forceinline__ void   st4(float* p, float4 v){ *reinterpret_cast<float4*>(p) = v; }
__device__ __forceinline__ float4 fma4(float a, float4 b, float4 c){
    c.x = fmaf(a,b.x,c.x); c.y = fmaf(a,b.y,c.y);
    c.z = fmaf(a,b.z,c.z); c.w = fmaf(a,b.w,c.w);
    return c;
}
__device__ __forceinline__ float dot4acc(float4 a, float4 b, float c){
    c = fmaf(a.x,b.x,c); c = fmaf(a.y,b.y,c);
    c = fmaf(a.z,b.z,c); c = fmaf(a.w,b.w,c);
    return c;
}

__global__ __launch_bounds__(BDIM, 2)
void rkn_kernel(const float* __restrict__ g_mean,
                const float* __restrict__ g_cov,
                const float* __restrict__ g_obs,
                const float* __restrict__ g_w1,
                const float* __restrict__ g_b1,
                const float* __restrict__ g_w2,
                const float* __restrict__ g_b2,
                const float* __restrict__ g_basis,
                const float* __restrict__ g_pnf,
                const float* __restrict__ g_pnd,
                const float* __restrict__ g_onf,
                const float* __restrict__ g_ond,
                const float* __restrict__ g_Hw,
                const float* __restrict__ g_Hb,
                float* __restrict__ o_mean,
                float* __restrict__ o_cov,
                float* __restrict__ o_ll)
{
    extern __shared__ float smem[];
    float* sP    = smem + OFF_P;
    float* sFt   = smem + OFF_FT;
    float* sT    = smem + OFF_T;
    float* sHw   = smem + OFF_HW;
    float* sHP   = smem + OFF_HP;    // union over sT
    float* sS    = smem + OFF_S;     // union over sFt
    float* sRcp  = smem + OFF_RECIP;
    float* sZ    = smem + OFF_Z;
    float* sm_   = smem + OFF_M;
    float* spm   = smem + OFF_PM;
    float* sinn  = smem + OFF_INN;
    float* sh    = smem + OFF_H;
    float* sw    = smem + OFF_W;
    float* sWv   = smem + OFF_WV;
    float* sred  = smem + OFF_RED;

    const int b   = blockIdx.x;
    const int tid = threadIdx.x;
    const int tx  = tid & 15;
    const int ty  = tid >> 4;

    // ---------------- loads ----------------
    if (tid < DD) sm_[tid] = g_mean[b*DD + tid];
    {   // Hw: 2048 floats
        int base = tid * 8;
        int r = base >> 6, c = base & 63;
        st4(sHw + r*PITCH + c,     ld4(g_Hw + base));
        st4(sHw + r*PITCH + c + 4, ld4(g_Hw + base + 4));
    }
    {   // P: 4096 floats
        const float* Pg = g_cov + (size_t)b*DD*DD;
        int base = tid*16;
        #pragma unroll
        for (int q=0;q<4;q++){
            int g = base + q*4;
            st4(sP + (g>>6)*PITCH + (g&63), ld4(Pg + g));
        }
    }
    __syncthreads();

    // ---------------- MLP layer 1 ----------------
    if (tid < HIDN) {
        float acc = g_b1[tid];
        const float* w1r = g_w1 + tid*DD;
        #pragma unroll 16
        for (int d=0; d<DD; d++) acc = fmaf(w1r[d], sm_[d], acc);
        sh[tid] = acc > 0.f ? acc : expm1f(acc);   // elu
    }
    __syncthreads();

    // ---------------- MLP layer 2 + softmax (fused, warp 0 lanes 0..15) ----------------
    if (tid < 16) {
        float acc = -1e30f;
        if (tid < KMIX) {
            acc = g_b2[tid];
            const float* w2r = g_w2 + tid*HIDN;
            #pragma unroll 15
            for (int j=0;j<HIDN;j++) acc = fmaf(w2r[j], sh[j], acc);
        }
        float mx = acc;
        #pragma unroll
        for (int off=8;off;off>>=1) mx = fmaxf(mx, __shfl_xor_sync(0xFFFFu, mx, off));
        float e = expf(acc - mx);
        float s = e;
        #pragma unroll
        for (int off=8;off;off>>=1) s += __shfl_xor_sync(0xFFFFu, s, off);
        if (tid < KMIX) sw[tid] = e / s;
    }
    __syncthreads();

    // ---------------- F = sum_k w_k basis_k (stored transposed) ----------------
    {
        float wl[KMIX];
        #pragma unroll
        for (int k=0;k<KMIX;k++) wl[k] = sw[k];
        int base = tid*16;
        int r = base >> 6;
        #pragma unroll
        for (int q=0;q<4;q++){
            int g = base + q*4;
            float4 acc = make_float4(0.f,0.f,0.f,0.f);
            #pragma unroll
            for (int k=0;k<KMIX;k++){
                float4 v = ld4(g_basis + k*4096 + g);
                acc = fma4(wl[k], v, acc);
            }
            int c = g & 63;
            sFt[(c+0)*PITCH + r] = acc.x;
            sFt[(c+1)*PITCH + r] = acc.y;
            sFt[(c+2)*PITCH + r] = acc.z;
            sFt[(c+3)*PITCH + r] = acc.w;
        }
    }
    __syncthreads();

    // pred_mean = F @ m
    if (tid < DD) {
        float acc = 0.f;
        #pragma unroll 16
        for (int k=0;k<DD;k++) acc = fmaf(sFt[k*PITCH + tid], sm_[k], acc);
        spm[tid] = acc;
    }

    // ---------------- GEMM1: T = F @ P ----------------
    {
        const int r0 = ty*4, c0 = tx*4;
        float4 acc0=make_float4(0,0,0,0), acc1=acc0, acc2=acc0, acc3=acc0;
        for (int k=0;k<DD;k+=4){
            float4 a0 = ld4(sFt + (k+0)*PITCH + r0);
            float4 a1 = ld4(sFt + (k+1)*PITCH + r0);
            float4 a2 = ld4(sFt + (k+2)*PITCH + r0);
            float4 a3 = ld4(sFt + (k+3)*PITCH + r0);
            float4 p0 = ld4(sP + (k+0)*PITCH + c0);
            acc0=fma4(a0.x,p0,acc0); acc1=fma4(a0.y,p0,acc1); acc2=fma4(a0.z,p0,acc2); acc3=fma4(a0.w,p0,acc3);
            float4 p1 = ld4(sP + (k+1)*PITCH + c0);
            acc0=fma4(a1.x,p1,acc0); acc1=fma4(a1.y,p1,acc1); acc2=fma4(a1.z,p1,acc2); acc3=fma4(a1.w,p1,acc3);
            float4 p2 = ld4(sP + (k+2)*PITCH + c0);
            acc0=fma4(a2.x,p2,acc0); acc1=fma4(a2.y,p2,acc1); acc2=fma4(a2.z,p2,acc2); acc3=fma4(a2.w,p2,acc3);
            float4 p3 = ld4(sP + (k+3)*PITCH + c0);
            acc0=fma4(a3.x,p3,acc0); acc1=fma4(a3.y,p3,acc1); acc2=fma4(a3.z,p3,acc2); acc3=fma4(a3.w,p3,acc3);
        }
        st4(sT + (r0+0)*PITCH + c0, acc0);
        st4(sT + (r0+1)*PITCH + c0, acc1);
        st4(sT + (r0+2)*PITCH + c0, acc2);
        st4(sT + (r0+3)*PITCH + c0, acc3);
    }
    __syncthreads();

    // innovation
    if (tid < OO) {
        float acc = g_Hb[tid];
        #pragma unroll 8
        for (int k=0;k<DD;k++) acc = fmaf(sHw[tid*PITCH+k], spm[k], acc);
        sinn[tid] = g_obs[b*OO + tid] - acc;
    }

    // ---------------- GEMM2: pred_cov = T @ F^T + Q (into sP, in place) ----------------
    {
        const int r0 = ty*4, c0 = tx*4;
        float4 acc0=make_float4(0,0,0,0), acc1=acc0, acc2=acc0, acc3=acc0;
        for (int k=0;k<DD;k+=4){
            float4 t0 = ld4(sT + (r0+0)*PITCH + k);
            float4 t1 = ld4(sT + (r0+1)*PITCH + k);
            float4 t2 = ld4(sT + (r0+2)*PITCH + k);
            float4 t3 = ld4(sT + (r0+3)*PITCH + k);
            float4 f0 = ld4(sFt + (k+0)*PITCH + c0);
            acc0=fma4(t0.x,f0,acc0); acc1=fma4(t1.x,f0,acc1); acc2=fma4(t2.x,f0,acc2); acc3=fma4(t3.x,f0,acc3);
            float4 f1 = ld4(sFt + (k+1)*PITCH + c0);
            acc0=fma4(t0.y,f1,acc0); acc1=fma4(t1.y,f1,acc1); acc2=fma4(t2.y,f1,acc2); acc3=fma4(t3.y,f1,acc3);
            float4 f2 = ld4(sFt + (k+2)*PITCH + c0);
            acc0=fma4(t0.z,f2,acc0); acc1=fma4(t1.z,f2,acc1); acc2=fma4(t2.z,f2,acc2); acc3=fma4(t3.z,f2,acc3);
            float4 f3 = ld4(sFt + (k+3)*PITCH + c0);
            acc0=fma4(t0.w,f3,acc0); acc1=fma4(t1.w,f3,acc1); acc2=fma4(t2.w,f3,acc2); acc3=fma4(t3.w,f3,acc3);
        }
        float pa[4][3], pb[4][3];
        #pragma unroll
        for (int i=0;i<4;i++)
            #pragma unroll
            for (int r=0;r<3;r++){
                pa[i][r] = g_pnf[(r0+i)*3 + r];
                pb[i][r] = g_pnf[(c0+i)*3 + r];
            }
        float* accp[4] = { &acc0.x, &acc1.x, &acc2.x, &acc3.x };
        #pragma unroll
        for (int i=0;i<4;i++){
            #pragma unroll
            for (int j=0;j<4;j++){
                float q = pa[i][0]*pb[j][0];
                q = fmaf(pa[i][1], pb[j][1], q);
                q = fmaf(pa[i][2], pb[j][2], q);
                accp[i][j] += q;
            }
        }
        if (r0 == c0){
            #pragma unroll
            for (int i=0;i<4;i++) accp[i][i] += expf(g_pnd[r0+i]);
        }
        st4(sP + (r0+0)*PITCH + c0, acc0);
        st4(sP + (r0+1)*PITCH + c0, acc1);
        st4(sP + (r0+2)*PITCH + c0, acc2);
        st4(sP + (r0+3)*PITCH + c0, acc3);
    }
    __syncthreads();

    // ---------------- HP = Hw @ pred_cov  [32][64]  (into old sT space) ----------------
    {
        const int o0 = ty*2, c0 = tx*4;
        float4 accA = make_float4(0,0,0,0), accB = accA;
        for (int k=0;k<DD;k+=4){
            float4 h0 = ld4(sHw + (o0+0)*PITCH + k);
            float4 h1 = ld4(sHw + (o0+1)*PITCH + k);
            float4 p0 = ld4(sP + (k+0)*PITCH + c0);
            accA=fma4(h0.x,p0,accA); accB=fma4(h1.x,p0,accB);
            float4 p1 = ld4(sP + (k+1)*PITCH + c0);
            accA=fma4(h0.y,p1,accA); accB=fma4(h1.y,p1,accB);
            float4 p2 = ld4(sP + (k+2)*PITCH + c0);
            accA=fma4(h0.z,p2,accA); accB=fma4(h1.z,p2,accB);
            float4 p3 = ld4(sP + (k+3)*PITCH + c0);
            accA=fma4(h0.w,p3,accA); accB=fma4(h1.w,p3,accB);
        }
        st4(sHP + (o0+0)*PITCH + c0, accA);
        st4(sHP + (o0+1)*PITCH + c0, accB);
    }
    __syncthreads();

    // ---------------- S = HP @ Hw^T + Rn  (into old sFt space) ----------------
    {
        const int o0 = ty*2, p0 = tx*2;
        float a00=0.f,a01=0.f,a10=0.f,a11=0.f;
        for (int k=0;k<DD;k+=4){
            float4 x0 = ld4(sHP + (o0+0)*PITCH + k);
            float4 x1 = ld4(sHP + (o0+1)*PITCH + k);
            float4 y0 = ld4(sHw + (p0+0)*PITCH + k);
            float4 y1 = ld4(sHw + (p0+1)*PITCH + k);
            a00 = dot4acc(x0,y0,a00); a01 = dot4acc(x0,y1,a01);
            a10 = dot4acc(x1,y0,a10); a11 = dot4acc(x1,y1,a11);
        }
        float oa[2][3], ob[2][3];
        #pragma unroll
        for (int i=0;i<2;i++)
            #pragma unroll
            for (int r=0;r<3;r++){
                oa[i][r] = g_onf[(o0+i)*3 + r];
                ob[i][r] = g_onf[(p0+i)*3 + r];
            }
        a00 += oa[0][0]*ob[0][0] + oa[0][1]*ob[0][1] + oa[0][2]*ob[0][2];
        a01 += oa[0][0]*ob[1][0] + oa[0][1]*ob[1][1] + oa[0][2]*ob[1][2];
        a10 += oa[1][0]*ob[0][0] + oa[1][1]*ob[0][1] + oa[1][2]*ob[0][2];
        a11 += oa[1][0]*ob[1][0] + oa[1][1]*ob[1][1] + oa[1][2]*ob[1][2];
        if (o0 == p0){
            a00 += expf(g_ond[o0+0]);
            a11 += expf(g_ond[o0+1]);
        }
        sS[(o0+0)*SPITCH + p0+0] = a00;
        sS[(o0+0)*SPITCH + p0+1] = a01;
        sS[(o0+1)*SPITCH + p0+0] = a10;
        sS[(o0+1)*SPITCH + p0+1] = a11;
    }
    __syncthreads();

    // ---------------- Cholesky (in place) + log_det + recip diag : warp 0 ----------------
    if (tid < 32) {
        const int i = tid;
        for (int j=0;j<32;j++){
            float s = 0.f;
            if (i >= j){
                s = sS[i*SPITCH + j];
                for (int k=0;k<j;k++) s = fmaf(-sS[i*SPITCH+k], sS[j*SPITCH+k], s);
            }
            float dj  = __shfl_sync(0xffffffffu, s, j);
            float ljj = sqrtf(dj);
            if (i == j)      sS[i*SPITCH+j] = ljj;
            else if (i > j)  sS[i*SPITCH+j] = s / ljj;
            __syncwarp();
        }
        float di = sS[i*SPITCH+i];
        sRcp[i] = 1.0f / di;
        float ld = logf(di);
        #pragma unroll
        for (int off=16;off;off>>=1) ld += __shfl_xor_sync(0xffffffffu, ld, off);
        if (i == 0) sred[0] = 2.f*ld;
    }
    __syncthreads();

    // ---------------- Triangular solves:  S * [Z | w] = [HP | inn] ----------------
    if (tid < 65) {
        float y[OO];
        if (tid < 64) {
            #pragma unroll
            for (int o=0;o<OO;o++) y[o] = sHP[o*PITCH + tid];
        } else {
            #pragma unroll
            for (int o=0;o<OO;o++) y[o] = sinn[o];
        }
        // forward: L y = rhs
        #pragma unroll
        for (int r=0;r<OO;r++){
            float acc = y[r];
            #pragma unroll
            for (int k=0;k<r;k++) acc = fmaf(-sS[r*SPITCH+k], y[k], acc);
            y[r] = acc * sRcp[r];
        }
        float quad = 0.f;
        if (tid == 64){
            #pragma unroll
            for (int o=0;o<OO;o++) quad = fmaf(y[o], y[o], quad);
        }
        // backward: L^T x = y
        #pragma unroll
        for (int r=OO-1;r>=0;r--){
            float acc = y[r];
            #pragma unroll
            for (int k=r+1;k<OO;k++) acc = fmaf(-sS[k*SPITCH+r], y[k], acc);
            y[r] = acc * sRcp[r];
        }
        if (tid < 64) {
            #pragma unroll
            for (int o=0;o<OO;o++) sZ[o*PITCH + tid] = y[o];
        } else {
            #pragma unroll
            for (int o=0;o<OO;o++) sWv[o] = y[o];
            sred[1] = quad;
        }
    }
    __syncthreads();

    // ---------------- outputs ----------------
    if (tid < DD) {           // post_mean = pred_mean + (HP)^T w
        float acc = spm[tid];
        #pragma unroll 8
        for (int o=0;o<OO;o++) acc = fmaf(sHP[o*PITCH+tid], sWv[o], acc);
        o_mean[(size_t)b*DD + tid] = acc;
    }
    if (tid == 64) {
        o_ll[b] = -0.5f*(sred[0] + sred[1] + 32.f*LOG2PI);
    }

    // post_cov = pred_cov - (HP)^T Z
    {
        const int r0 = ty*4, c0 = tx*4;
        float4 acc0=make_float4(0,0,0,0), acc1=acc0, acc2=acc0, acc3=acc0;
        #pragma unroll 4
        for (int o=0;o<OO;o++){
            float4 a = ld4(sHP + o*PITCH + r0);
            float4 z = ld4(sZ  + o*PITCH + c0);
            acc0 = fma4(a.x, z, acc0);
            acc1 = fma4(a.y, z, acc1);
            acc2 = fma4(a.z, z, acc2);
            acc3 = fma4(a.w, z, acc3);
        }
        float* outr = o_cov + (size_t)b*4096;
        float4 accs[4] = {acc0, acc1, acc2, acc3};
        #pragma unroll
        for (int i=0;i<4;i++){
            float4 pc = ld4(sP + (r0+i)*PITCH + c0);
            float4 res = make_float4(pc.x - accs[i].x, pc.y - accs[i].y,
                                     pc.z - accs[i].z, pc.w - accs[i].w);
            st4(outr + (r0+i)*64 + c0, res);
        }
    }
}

extern "C" void kernel_launch(void* const* d_in, const int* in_sizes, int n_in,
                              void* d_out, int out_size)
{
    const float* g_mean  = (const float*)d_in[0];
    const float* g_cov   = (const float*)d_in[1];
    const float* g_obs   = (const float*)d_in[2];
    const float* g_w1    = (const float*)d_in[3];
    const float* g_b1    = (const float*)d_in[4];
    const float* g_w2    = (const float*)d_in[5];
    const float* g_b2    = (const float*)d_in[6];
    const float* g_basis = (const float*)d_in[7];
    const float* g_pnf   = (const float*)d_in[8];
    const float* g_pnd   = (const float*)d_in[9];
    const float* g_onf   = (const float*)d_in[10];
    const float* g_ond   = (const float*)d_in[11];
    const float* g_Hw    = (const float*)d_in[12];
    const float* g_Hb    = (const float*)d_in[13];

    const int B = in_sizes[0] / DD;
    float* out    = (float*)d_out;
    float* o_mean = out;
    float* o_cov  = out + (size_t)B*DD;
    float* o_ll   = out + (size_t)B*DD + (size_t)B*DD*DD;

    const int smem_bytes = SMEM_FLOATS * (int)sizeof(float);
    cudaFuncSetAttribute(rkn_kernel, cudaFuncAttributeMaxDynamicSharedMemorySize, smem_bytes);
    rkn_kernel<<<B, BDIM, smem_bytes>>>(g_mean, g_cov, g_obs, g_w1, g_b1, g_w2, g_b2,
                                        g_basis, g_pnf, g_pnd, g_onf, g_ond, g_Hw, g_Hb,
                                        o_mean, o_cov, o_ll);
}

// round 4
// speedup vs baseline: 1.2679x; 1.2115x over previous
#include <cuda_runtime.h>
#include <math.h>

#define DD     64
#define OO     32
#define KMIX   15
#define HIDN   60
#define FPITCH 68
#define SPITCH 36
#define UPITCH 68   // HP/U rows: 64 data cols + col 64 = innovation/v
#define LOG2PI 1.8378770664093453f
#define BMAX   8192

// ---------------- scratch (static device globals; no allocation) ----------------
__device__ float scr_cov[(size_t)BMAX*4096];   // pred_cov, row-major 64x64
__device__ float scr_hp [(size_t)BMAX*2176];   // HP rows pitch 68; col 64 = innovation
__device__ float scr_s  [(size_t)BMAX*1024];   // S, 32x32
__device__ float scr_pm [(size_t)BMAX*64];     // pred_mean

__device__ __forceinline__ float4 ld4(const float* p){ return *reinterpret_cast<const float4*>(p); }
__device__ __forceinline__ void   st4(float* p, float4 v){ *reinterpret_cast<float4*>(p) = v; }
__device__ __forceinline__ float4 fma4(float a, float4 b, float4 c){
    c.x = fmaf(a,b.x,c.x); c.y = fmaf(a,b.y,c.y);
    c.z = fmaf(a,b.z,c.z); c.w = fmaf(a,b.w,c.w);
    return c;
}
__device__ __forceinline__ float dot4acc(float4 a, float4 b, float c){
    c = fmaf(a.x,b.x,c); c = fmaf(a.y,b.y,c);
    c = fmaf(a.z,b.z,c); c = fmaf(a.w,b.w,c);
    return c;
}

// ================= Kernel 1: predict (256 threads, 4 CTAs/SM) =================
// smem: sP 64x64 (4096) | sFt 64x68 (4352, union sHP 32x68 after GEMM2) | sT 64x64 (4096) | misc
#define K1_OFF_P   0
#define K1_OFF_FT  (K1_OFF_P  + DD*DD)
#define K1_OFF_T   (K1_OFF_FT + DD*FPITCH)
#define K1_OFF_M   (K1_OFF_T  + DD*DD)
#define K1_OFF_PM  (K1_OFF_M  + DD)
#define K1_OFF_H   (K1_OFF_PM + DD)
#define K1_OFF_W   (K1_OFF_H  + DD)
#define K1_FLOATS  (K1_OFF_W  + 16)
#define K1_OFF_HP  K1_OFF_FT

__global__ __launch_bounds__(256, 4)
void rkn_predict(const float* __restrict__ g_mean,
                 const float* __restrict__ g_cov,
                 const float* __restrict__ g_obs,
                 const float* __restrict__ g_w1,
                 const float* __restrict__ g_b1,
                 const float* __restrict__ g_w2,
                 const float* __restrict__ g_b2,
                 const float* __restrict__ g_basis,
                 const float* __restrict__ g_pnf,
                 const float* __restrict__ g_pnd,
                 const float* __restrict__ g_onf,
                 const float* __restrict__ g_ond,
                 const float* __restrict__ g_Hw,
                 const float* __restrict__ g_Hb)
{
    extern __shared__ float smem[];
    float* sP  = smem + K1_OFF_P;
    float* sFt = smem + K1_OFF_FT;
    float* sT  = smem + K1_OFF_T;
    float* sHP = smem + K1_OFF_HP;   // union over sFt (after GEMM2)
    float* sm_ = smem + K1_OFF_M;
    float* spm = smem + K1_OFF_PM;
    float* sh  = smem + K1_OFF_H;
    float* sw  = smem + K1_OFF_W;

    const int b   = blockIdx.x;
    const int tid = threadIdx.x;
    const int tx  = tid & 15;
    const int ty  = tid >> 4;

    // loads
    if (tid < DD) sm_[tid] = g_mean[b*DD + tid];
    {   // P: direct copy (pitch 64)
        const float* Pg = g_cov + (size_t)b*DD*DD;
        int base = tid*16;
        #pragma unroll
        for (int q=0;q<4;q++) st4(sP + base + q*4, ld4(Pg + base + q*4));
    }
    __syncthreads();

    // MLP layer 1
    if (tid < HIDN) {
        float acc = g_b1[tid];
        const float* w1r = g_w1 + tid*DD;
        #pragma unroll 16
        for (int d=0; d<DD; d++) acc = fmaf(w1r[d], sm_[d], acc);
        sh[tid] = acc > 0.f ? acc : expm1f(acc);
    }
    __syncthreads();

    // MLP layer 2 + softmax (warp 0 lanes 0..15)
    if (tid < 16) {
        float acc = -1e30f;
        if (tid < KMIX) {
            acc = g_b2[tid];
            const float* w2r = g_w2 + tid*HIDN;
            #pragma unroll 15
            for (int j=0;j<HIDN;j++) acc = fmaf(w2r[j], sh[j], acc);
        }
        float mx = acc;
        #pragma unroll
        for (int off=8;off;off>>=1) mx = fmaxf(mx, __shfl_xor_sync(0xFFFFu, mx, off));
        float e = expf(acc - mx);
        float s = e;
        #pragma unroll
        for (int off=8;off;off>>=1) s += __shfl_xor_sync(0xFFFFu, s, off);
        if (tid < KMIX) sw[tid] = e / s;
    }
    __syncthreads();

    // F = sum_k w_k basis_k, stored transposed (pitch 68)
    {
        float wl[KMIX];
        #pragma unroll
        for (int k=0;k<KMIX;k++) wl[k] = sw[k];
        int base = tid*16;
        int r = base >> 6;
        #pragma unroll
        for (int q=0;q<4;q++){
            int g = base + q*4;
            float4 acc = make_float4(0.f,0.f,0.f,0.f);
            #pragma unroll
            for (int k=0;k<KMIX;k++){
                float4 v = ld4(g_basis + k*4096 + g);
                acc = fma4(wl[k], v, acc);
            }
            int c = g & 63;
            sFt[(c+0)*FPITCH + r] = acc.x;
            sFt[(c+1)*FPITCH + r] = acc.y;
            sFt[(c+2)*FPITCH + r] = acc.z;
            sFt[(c+3)*FPITCH + r] = acc.w;
        }
    }
    __syncthreads();

    // pred_mean = F @ m
    if (tid < DD) {
        float acc = 0.f;
        #pragma unroll 16
        for (int k=0;k<DD;k++) acc = fmaf(sFt[k*FPITCH + tid], sm_[k], acc);
        spm[tid] = acc;
        scr_pm[(size_t)b*DD + tid] = acc;
    }

    // GEMM1: T = F @ P
    {
        const int r0 = ty*4, c0 = tx*4;
        float4 acc0=make_float4(0,0,0,0), acc1=acc0, acc2=acc0, acc3=acc0;
        for (int k=0;k<DD;k+=4){
            float4 a0 = ld4(sFt + (k+0)*FPITCH + r0);
            float4 a1 = ld4(sFt + (k+1)*FPITCH + r0);
            float4 a2 = ld4(sFt + (k+2)*FPITCH + r0);
            float4 a3 = ld4(sFt + (k+3)*FPITCH + r0);
            float4 p0 = ld4(sP + (k+0)*DD + c0);
            acc0=fma4(a0.x,p0,acc0); acc1=fma4(a0.y,p0,acc1); acc2=fma4(a0.z,p0,acc2); acc3=fma4(a0.w,p0,acc3);
            float4 p1 = ld4(sP + (k+1)*DD + c0);
            acc0=fma4(a1.x,p1,acc0); acc1=fma4(a1.y,p1,acc1); acc2=fma4(a1.z,p1,acc2); acc3=fma4(a1.w,p1,acc3);
            float4 p2 = ld4(sP + (k+2)*DD + c0);
            acc0=fma4(a2.x,p2,acc0); acc1=fma4(a2.y,p2,acc1); acc2=fma4(a2.z,p2,acc2); acc3=fma4(a2.w,p2,acc3);
            float4 p3 = ld4(sP + (k+3)*DD + c0);
            acc0=fma4(a3.x,p3,acc0); acc1=fma4(a3.y,p3,acc1); acc2=fma4(a3.z,p3,acc2); acc3=fma4(a3.w,p3,acc3);
        }
        st4(sT + (r0+0)*DD + c0, acc0);
        st4(sT + (r0+1)*DD + c0, acc1);
        st4(sT + (r0+2)*DD + c0, acc2);
        st4(sT + (r0+3)*DD + c0, acc3);
    }
    __syncthreads();

    // innovation -> scr_hp column 64
    if (tid < OO) {
        float acc = g_Hb[tid];
        const float* hwr = g_Hw + tid*DD;
        #pragma unroll 8
        for (int k=0;k<DD;k++) acc = fmaf(hwr[k], spm[k], acc);
        scr_hp[(size_t)b*2176 + tid*UPITCH + 64] = g_obs[b*OO + tid] - acc;
    }

    // GEMM2: pred_cov = T @ F^T + Q -> sP (in place) + scr_cov
    {
        const int r0 = ty*4, c0 = tx*4;
        float4 acc0=make_float4(0,0,0,0), acc1=acc0, acc2=acc0, acc3=acc0;
        for (int k=0;k<DD;k+=4){
            float4 t0 = ld4(sT + (r0+0)*DD + k);
            float4 t1 = ld4(sT + (r0+1)*DD + k);
            float4 t2 = ld4(sT + (r0+2)*DD + k);
            float4 t3 = ld4(sT + (r0+3)*DD + k);
            float4 f0 = ld4(sFt + (k+0)*FPITCH + c0);
            acc0=fma4(t0.x,f0,acc0); acc1=fma4(t1.x,f0,acc1); acc2=fma4(t2.x,f0,acc2); acc3=fma4(t3.x,f0,acc3);
            float4 f1 = ld4(sFt + (k+1)*FPITCH + c0);
            acc0=fma4(t0.y,f1,acc0); acc1=fma4(t1.y,f1,acc1); acc2=fma4(t2.y,f1,acc2); acc3=fma4(t3.y,f1,acc3);
            float4 f2 = ld4(sFt + (k+2)*FPITCH + c0);
            acc0=fma4(t0.z,f2,acc0); acc1=fma4(t1.z,f2,acc1); acc2=fma4(t2.z,f2,acc2); acc3=fma4(t3.z,f2,acc3);
            float4 f3 = ld4(sFt + (k+3)*FPITCH + c0);
            acc0=fma4(t0.w,f3,acc0); acc1=fma4(t1.w,f3,acc1); acc2=fma4(t2.w,f3,acc2); acc3=fma4(t3.w,f3,acc3);
        }
        float pa[4][3], pb[4][3];
        #pragma unroll
        for (int i=0;i<4;i++)
            #pragma unroll
            for (int r=0;r<3;r++){
                pa[i][r] = g_pnf[(r0+i)*3 + r];
                pb[i][r] = g_pnf[(c0+i)*3 + r];
            }
        float* accp[4] = { &acc0.x, &acc1.x, &acc2.x, &acc3.x };
        #pragma unroll
        for (int i=0;i<4;i++){
            #pragma unroll
            for (int j=0;j<4;j++){
                float q = pa[i][0]*pb[j][0];
                q = fmaf(pa[i][1], pb[j][1], q);
                q = fmaf(pa[i][2], pb[j][2], q);
                accp[i][j] += q;
            }
        }
        if (r0 == c0){
            #pragma unroll
            for (int i=0;i<4;i++) accp[i][i] += expf(g_pnd[r0+i]);
        }
        float* cg = scr_cov + (size_t)b*4096;
        st4(sP + (r0+0)*DD + c0, acc0);  st4(cg + (r0+0)*DD + c0, acc0);
        st4(sP + (r0+1)*DD + c0, acc1);  st4(cg + (r0+1)*DD + c0, acc1);
        st4(sP + (r0+2)*DD + c0, acc2);  st4(cg + (r0+2)*DD + c0, acc2);
        st4(sP + (r0+3)*DD + c0, acc3);  st4(cg + (r0+3)*DD + c0, acc3);
    }
    __syncthreads();

    // HP = Hw @ pred_cov  (Hw from global/L1) -> sHP (pitch 68) + scr_hp
    {
        const int o0 = ty*2, c0 = tx*4;
        float4 accA = make_float4(0,0,0,0), accB = accA;
        const float* hw0 = g_Hw + (o0+0)*DD;
        const float* hw1 = g_Hw + (o0+1)*DD;
        for (int k=0;k<DD;k+=4){
            float4 h0 = ld4(hw0 + k);
            float4 h1 = ld4(hw1 + k);
            float4 p0 = ld4(sP + (k+0)*DD + c0);
            accA=fma4(h0.x,p0,accA); accB=fma4(h1.x,p0,accB);
            float4 p1 = ld4(sP + (k+1)*DD + c0);
            accA=fma4(h0.y,p1,accA); accB=fma4(h1.y,p1,accB);
            float4 p2 = ld4(sP + (k+2)*DD + c0);
            accA=fma4(h0.z,p2,accA); accB=fma4(h1.z,p2,accB);
            float4 p3 = ld4(sP + (k+3)*DD + c0);
            accA=fma4(h0.w,p3,accA); accB=fma4(h1.w,p3,accB);
        }
        float* hg = scr_hp + (size_t)b*2176;
        st4(sHP + (o0+0)*UPITCH + c0, accA);  st4(hg + (o0+0)*UPITCH + c0, accA);
        st4(sHP + (o0+1)*UPITCH + c0, accB);  st4(hg + (o0+1)*UPITCH + c0, accB);
    }
    __syncthreads();

    // S = HP @ Hw^T + Rn -> scr_s
    {
        const int o0 = ty*2, p0 = tx*2;
        float a00=0.f,a01=0.f,a10=0.f,a11=0.f;
        const float* hw0 = g_Hw + (p0+0)*DD;
        const float* hw1 = g_Hw + (p0+1)*DD;
        for (int k=0;k<DD;k+=4){
            float4 x0 = ld4(sHP + (o0+0)*UPITCH + k);
            float4 x1 = ld4(sHP + (o0+1)*UPITCH + k);
            float4 y0 = ld4(hw0 + k);
            float4 y1 = ld4(hw1 + k);
            a00 = dot4acc(x0,y0,a00); a01 = dot4acc(x0,y1,a01);
            a10 = dot4acc(x1,y0,a10); a11 = dot4acc(x1,y1,a11);
        }
        float oa[2][3], ob[2][3];
        #pragma unroll
        for (int i=0;i<2;i++)
            #pragma unroll
            for (int r=0;r<3;r++){
                oa[i][r] = g_onf[(o0+i)*3 + r];
                ob[i][r] = g_onf[(p0+i)*3 + r];
            }
        a00 += oa[0][0]*ob[0][0] + oa[0][1]*ob[0][1] + oa[0][2]*ob[0][2];
        a01 += oa[0][0]*ob[1][0] + oa[0][1]*ob[1][1] + oa[0][2]*ob[1][2];
        a10 += oa[1][0]*ob[0][0] + oa[1][1]*ob[0][1] + oa[1][2]*ob[0][2];
        a11 += oa[1][0]*ob[1][0] + oa[1][1]*ob[1][1] + oa[1][2]*ob[1][2];
        if (o0 == p0){
            a00 += expf(g_ond[o0+0]);
            a11 += expf(g_ond[o0+1]);
        }
        float* sg = scr_s + (size_t)b*1024;
        sg[(o0+0)*OO + p0+0] = a00;
        sg[(o0+0)*OO + p0+1] = a01;
        sg[(o0+1)*OO + p0+0] = a10;
        sg[(o0+1)*OO + p0+1] = a11;
    }
}

// ================= Kernel 2: update (128 threads, small smem) =================
// post_cov = pred_cov - U^T U ;  post_mean = pm + U^T v ;  quad = v^T v
// where [U | v] = forward_solve(L, [HP | inn]) done in place, columns thread-private.
#define K2_OFF_S   0
#define K2_OFF_RCP (K2_OFF_S   + OO*SPITCH)
#define K2_OFF_U   (K2_OFF_RCP + 32)
#define K2_OFF_PM  (K2_OFF_U   + OO*UPITCH)
#define K2_OFF_RED (K2_OFF_PM  + DD)
#define K2_FLOATS  (K2_OFF_RED + 4)

__global__ __launch_bounds__(128, 6)
void rkn_update(float* __restrict__ o_mean,
                float* __restrict__ o_cov,
                float* __restrict__ o_ll)
{
    extern __shared__ float smem[];
    float* sS   = smem + K2_OFF_S;
    float* sRcp = smem + K2_OFF_RCP;
    float* sU   = smem + K2_OFF_U;
    float* spm  = smem + K2_OFF_PM;
    float* sred = smem + K2_OFF_RED;

    const int b   = blockIdx.x;
    const int tid = threadIdx.x;

    // loads
    {
        const float* sg = scr_s + (size_t)b*1024;
        for (int i=tid;i<1024;i+=128) sS[(i>>5)*SPITCH + (i&31)] = sg[i];
        const float* hg = scr_hp + (size_t)b*2176;
        for (int i=tid;i<544;i+=128) st4(sU + i*4, ld4(hg + i*4));
        if (tid < DD) spm[tid] = scr_pm[(size_t)b*DD + tid];
    }
    __syncthreads();

    // Cholesky (warp 0) + recip diag + logdet
    if (tid < 32) {
        const int i = tid;
        for (int j=0;j<32;j++){
            float s = 0.f;
            if (i >= j){
                s = sS[i*SPITCH + j];
                for (int k=0;k<j;k++) s = fmaf(-sS[i*SPITCH+k], sS[j*SPITCH+k], s);
            }
            float dj  = __shfl_sync(0xffffffffu, s, j);
            float ljj = sqrtf(dj);
            if (i == j)      sS[i*SPITCH+j] = ljj;
            else if (i > j)  sS[i*SPITCH+j] = s / ljj;
            __syncwarp();
        }
        float di = sS[i*SPITCH+i];
        sRcp[i] = 1.0f / di;
        float ld = logf(di);
        #pragma unroll
        for (int off=16;off;off>>=1) ld += __shfl_xor_sync(0xffffffffu, ld, off);
        if (i == 0) sred[0] = 2.f*ld;
    }
    __syncthreads();

    // forward solve, in place: columns are thread-private (no cross-thread deps)
    if (tid < 65) {
        const int c = tid;
        for (int r=0;r<OO;r++){
            float val = sU[r*UPITCH + c];
            for (int k=0;k<r;k++) val = fmaf(-sS[r*SPITCH+k], sU[k*UPITCH + c], val);
            sU[r*UPITCH + c] = val * sRcp[r];
        }
    }
    __syncthreads();

    // log-likelihood (v is column 64 of U)
    if (tid == 64) {
        float quad = 0.f;
        #pragma unroll
        for (int o=0;o<OO;o++){ float v = sU[o*UPITCH + 64]; quad = fmaf(v, v, quad); }
        o_ll[b] = -0.5f*(sred[0] + quad + 32.f*LOG2PI);
    }

    // post_mean = pm + U^T v
    if (tid < DD) {
        float acc = spm[tid];
        #pragma unroll 8
        for (int o=0;o<OO;o++) acc = fmaf(sU[o*UPITCH + tid], sU[o*UPITCH + 64], acc);
        o_mean[(size_t)b*DD + tid] = acc;
    }

    // post_cov = pred_cov - U^T U   (8x4 tile per thread, 128 threads)
    {
        const int tx = tid & 15, ty = tid >> 4;
        const int r0 = ty*8, c0 = tx*4;
        float4 acc[8];
        #pragma unroll
        for (int i=0;i<8;i++) acc[i] = make_float4(0,0,0,0);
        #pragma unroll 4
        for (int o=0;o<OO;o++){
            float4 bv = ld4(sU + o*UPITCH + c0);
            float4 a0 = ld4(sU + o*UPITCH + r0);
            float4 a1 = ld4(sU + o*UPITCH + r0 + 4);
            acc[0]=fma4(a0.x,bv,acc[0]); acc[1]=fma4(a0.y,bv,acc[1]);
            acc[2]=fma4(a0.z,bv,acc[2]); acc[3]=fma4(a0.w,bv,acc[3]);
            acc[4]=fma4(a1.x,bv,acc[4]); acc[5]=fma4(a1.y,bv,acc[5]);
            acc[6]=fma4(a1.z,bv,acc[6]); acc[7]=fma4(a1.w,bv,acc[7]);
        }
        const float* cg = scr_cov + (size_t)b*4096;
        float* outr = o_cov + (size_t)b*4096;
        #pragma unroll
        for (int i=0;i<8;i++){
            float4 pc = ld4(cg + (r0+i)*DD + c0);
            st4(outr + (r0+i)*DD + c0,
                make_float4(pc.x - acc[i].x, pc.y - acc[i].y,
                            pc.z - acc[i].z, pc.w - acc[i].w));
        }
    }
}

extern "C" void kernel_launch(void* const* d_in, const int* in_sizes, int n_in,
                              void* d_out, int out_size)
{
    const float* g_mean  = (const float*)d_in[0];
    const float* g_cov   = (const float*)d_in[1];
    const float* g_obs   = (const float*)d_in[2];
    const float* g_w1    = (const float*)d_in[3];
    const float* g_b1    = (const float*)d_in[4];
    const float* g_w2    = (const float*)d_in[5];
    const float* g_b2    = (const float*)d_in[6];
    const float* g_basis = (const float*)d_in[7];
    const float* g_pnf   = (const float*)d_in[8];
    const float* g_pnd   = (const float*)d_in[9];
    const float* g_onf   = (const float*)d_in[10];
    const float* g_ond   = (const float*)d_in[11];
    const float* g_Hw    = (const float*)d_in[12];
    const float* g_Hb    = (const float*)d_in[13];

    int B = in_sizes[0] / DD;
    if (B > BMAX) B = BMAX;
    float* out    = (float*)d_out;
    float* o_mean = out;
    float* o_cov  = out + (size_t)B*DD;
    float* o_ll   = out + (size_t)B*DD + (size_t)B*DD*DD;

    const int k1_smem = K1_FLOATS * (int)sizeof(float);
    const int k2_smem = K2_FLOATS * (int)sizeof(float);
    cudaFuncSetAttribute(rkn_predict, cudaFuncAttributeMaxDynamicSharedMemorySize, k1_smem);
    cudaFuncSetAttribute(rkn_update,  cudaFuncAttributeMaxDynamicSharedMemorySize, k2_smem);

    rkn_predict<<<B, 256, k1_smem>>>(g_mean, g_cov, g_obs, g_w1, g_b1, g_w2, g_b2,
                                     g_basis, g_pnf, g_pnd, g_onf, g_ond, g_Hw, g_Hb);
    rkn_update <<<B, 128, k2_smem>>>(o_mean, o_cov, o_ll);
}

// round 5
// speedup vs baseline: 1.8071x; 1.4253x over previous
#include <cuda_runtime.h>
#include <math.h>

#define DD     64
#define OO     32
#define KMIX   15
#define HIDN   60
#define FPITCH 68
#define SPITCH 36
#define UPITCH 68
#define LOG2PI 1.8378770664093453f
#define BMAX   8192

// ---------------- scratch (static device globals; no allocation) ----------------
__device__ float scr_cov[(size_t)BMAX*4096];   // pred_cov
__device__ float scr_hp [(size_t)BMAX*2176];   // HP rows pitch 68 (col 64 unused by K1)
__device__ float scr_s  [(size_t)BMAX*1024];   // S 32x32
__device__ float scr_pm [(size_t)BMAX*64];     // pred_mean
__device__ float scr_w  [(size_t)BMAX*16];     // mixture weights (pitch 16)
__device__ float scr_f  [(size_t)BMAX*4096];   // F row-major

__device__ __forceinline__ float4 ld4(const float* p){ return *reinterpret_cast<const float4*>(p); }
__device__ __forceinline__ void   st4(float* p, float4 v){ *reinterpret_cast<float4*>(p) = v; }
__device__ __forceinline__ float4 fma4(float a, float4 b, float4 c){
    c.x = fmaf(a,b.x,c.x); c.y = fmaf(a,b.y,c.y);
    c.z = fmaf(a,b.z,c.z); c.w = fmaf(a,b.w,c.w);
    return c;
}
__device__ __forceinline__ float dot4acc(float4 a, float4 b, float c){
    c = fmaf(a.x,b.x,c); c = fmaf(a.y,b.y,c);
    c = fmaf(a.z,b.z,c); c = fmaf(a.w,b.w,c);
    return c;
}

// ========== K00: MLP + softmax -> scr_w  (warp per batch, 8 batches/CTA) ==========
__global__ __launch_bounds__(256)
void rkn_weights(const float* __restrict__ g_mean,
                 const float* __restrict__ g_w1,
                 const float* __restrict__ g_b1,
                 const float* __restrict__ g_w2,
                 const float* __restrict__ g_b2)
{
    __shared__ float sw1[HIDN*65];
    __shared__ float sw2[KMIX*HIDN];
    __shared__ float sb1[HIDN];
    __shared__ float sb2[KMIX];
    __shared__ float smn[8][64];
    __shared__ float shd[8][64];

    const int tid = threadIdx.x;
    for (int i=tid;i<HIDN*DD;i+=256){ int u=i>>6, d=i&63; sw1[u*65+d]=g_w1[i]; }
    for (int i=tid;i<KMIX*HIDN;i+=256) sw2[i]=g_w2[i];
    if (tid<HIDN) sb1[tid]=g_b1[tid];
    if (tid<KMIX) sb2[tid]=g_b2[tid];

    const int w = tid>>5, lane = tid&31;
    const int b = blockIdx.x*8 + w;
    smn[w][lane]    = g_mean[b*DD + lane];
    smn[w][lane+32] = g_mean[b*DD + 32 + lane];
    __syncthreads();

    {   // hidden layer
        float acc = sb1[lane];
        #pragma unroll 16
        for (int d=0;d<DD;d++) acc = fmaf(sw1[lane*65+d], smn[w][d], acc);
        shd[w][lane] = acc > 0.f ? acc : expm1f(acc);
        int u = lane + 32;
        if (u < HIDN) {
            float a2 = sb1[u];
            #pragma unroll 16
            for (int d=0;d<DD;d++) a2 = fmaf(sw1[u*65+d], smn[w][d], a2);
            shd[w][u] = a2 > 0.f ? a2 : expm1f(a2);
        }
    }
    __syncwarp();

    if (lane < 16) {   // logits + softmax on low half-warp
        float acc = -1e30f;
        if (lane < KMIX) {
            acc = sb2[lane];
            #pragma unroll 15
            for (int j=0;j<HIDN;j++) acc = fmaf(sw2[lane*HIDN+j], shd[w][j], acc);
        }
        float mx = acc;
        #pragma unroll
        for (int off=8;off;off>>=1) mx = fmaxf(mx, __shfl_xor_sync(0xFFFFu, mx, off));
        float e = expf(acc - mx);
        float s = e;
        #pragma unroll
        for (int off=8;off;off>>=1) s += __shfl_xor_sync(0xFFFFu, s, off);
        if (lane < KMIX) scr_w[(size_t)b*16 + lane] = e / s;
    }
}

// ========== K0: F_all = W @ basis  (16 batches x 1024 elems per CTA) ==========
__global__ __launch_bounds__(256)
void rkn_mixf(const float* __restrict__ g_basis)
{
    __shared__ float sW[16][16];
    const int tid = threadIdx.x;
    const int b0 = blockIdx.x*16;
    if (tid < 240) sW[tid/15][tid%15] = scr_w[(size_t)(b0 + tid/15)*16 + (tid%15)];
    __syncthreads();

    const int n = blockIdx.y*1024 + tid*4;
    float4 bs[KMIX];
    #pragma unroll
    for (int k=0;k<KMIX;k++) bs[k] = ld4(g_basis + k*4096 + n);

    #pragma unroll 4
    for (int bb=0;bb<16;bb++){
        float4 acc = make_float4(0.f,0.f,0.f,0.f);
        #pragma unroll
        for (int k=0;k<KMIX;k++) acc = fma4(sW[bb][k], bs[k], acc);
        st4(scr_f + (size_t)(b0+bb)*4096 + n, acc);
    }
}

// ========== K1: predict GEMMs (256 threads, 4 CTAs/SM) ==========
#define K1_OFF_P   0
#define K1_OFF_FT  (K1_OFF_P  + DD*DD)
#define K1_OFF_T   (K1_OFF_FT + DD*FPITCH)
#define K1_OFF_M   (K1_OFF_T  + DD*DD)
#define K1_OFF_PM  (K1_OFF_M  + DD)
#define K1_FLOATS  (K1_OFF_PM + DD)
#define K1_OFF_HP  K1_OFF_FT

__global__ __launch_bounds__(256, 4)
void rkn_predict(const float* __restrict__ g_mean,
                 const float* __restrict__ g_cov,
                 const float* __restrict__ g_pnf,
                 const float* __restrict__ g_pnd,
                 const float* __restrict__ g_onf,
                 const float* __restrict__ g_ond,
                 const float* __restrict__ g_Hw)
{
    extern __shared__ float smem[];
    float* sP  = smem + K1_OFF_P;
    float* sFt = smem + K1_OFF_FT;
    float* sT  = smem + K1_OFF_T;
    float* sHP = smem + K1_OFF_HP;   // union over sFt after GEMM2
    float* sm_ = smem + K1_OFF_M;
    float* spm = smem + K1_OFF_PM;

    const int b   = blockIdx.x;
    const int tid = threadIdx.x;
    const int tx  = tid & 15;
    const int ty  = tid >> 4;

    if (tid < DD) sm_[tid] = g_mean[b*DD + tid];
    {   // P
        const float* Pg = g_cov + (size_t)b*DD*DD;
        int base = tid*16;
        #pragma unroll
        for (int q=0;q<4;q++) st4(sP + base + q*4, ld4(Pg + base + q*4));
    }
    {   // F: coalesced load, scatter-transpose into sFt
        const float* Fg = scr_f + (size_t)b*4096;
        int base = tid*16;
        int i = base >> 6;
        #pragma unroll
        for (int q=0;q<4;q++){
            int g = base + q*4;
            float4 v = ld4(Fg + g);
            int j = g & 63;
            sFt[(j+0)*FPITCH + i] = v.x;
            sFt[(j+1)*FPITCH + i] = v.y;
            sFt[(j+2)*FPITCH + i] = v.z;
            sFt[(j+3)*FPITCH + i] = v.w;
        }
    }
    __syncthreads();

    // pred_mean = F @ m
    if (tid < DD) {
        float acc = 0.f;
        #pragma unroll 16
        for (int k=0;k<DD;k++) acc = fmaf(sFt[k*FPITCH + tid], sm_[k], acc);
        spm[tid] = acc;
        scr_pm[(size_t)b*DD + tid] = acc;
    }

    // GEMM1: T = F @ P
    {
        const int r0 = ty*4, c0 = tx*4;
        float4 acc0=make_float4(0,0,0,0), acc1=acc0, acc2=acc0, acc3=acc0;
        for (int k=0;k<DD;k+=4){
            float4 a0 = ld4(sFt + (k+0)*FPITCH + r0);
            float4 a1 = ld4(sFt + (k+1)*FPITCH + r0);
            float4 a2 = ld4(sFt + (k+2)*FPITCH + r0);
            float4 a3 = ld4(sFt + (k+3)*FPITCH + r0);
            float4 p0 = ld4(sP + (k+0)*DD + c0);
            acc0=fma4(a0.x,p0,acc0); acc1=fma4(a0.y,p0,acc1); acc2=fma4(a0.z,p0,acc2); acc3=fma4(a0.w,p0,acc3);
            float4 p1 = ld4(sP + (k+1)*DD + c0);
            acc0=fma4(a1.x,p1,acc0); acc1=fma4(a1.y,p1,acc1); acc2=fma4(a1.z,p1,acc2); acc3=fma4(a1.w,p1,acc3);
            float4 p2 = ld4(sP + (k+2)*DD + c0);
            acc0=fma4(a2.x,p2,acc0); acc1=fma4(a2.y,p2,acc1); acc2=fma4(a2.z,p2,acc2); acc3=fma4(a2.w,p2,acc3);
            float4 p3 = ld4(sP + (k+3)*DD + c0);
            acc0=fma4(a3.x,p3,acc0); acc1=fma4(a3.y,p3,acc1); acc2=fma4(a3.z,p3,acc2); acc3=fma4(a3.w,p3,acc3);
        }
        st4(sT + (r0+0)*DD + c0, acc0);
        st4(sT + (r0+1)*DD + c0, acc1);
        st4(sT + (r0+2)*DD + c0, acc2);
        st4(sT + (r0+3)*DD + c0, acc3);
    }
    __syncthreads();

    // GEMM2: pred_cov = T @ F^T + Q
    {
        const int r0 = ty*4, c0 = tx*4;
        float4 acc0=make_float4(0,0,0,0), acc1=acc0, acc2=acc0, acc3=acc0;
        for (int k=0;k<DD;k+=4){
            float4 t0 = ld4(sT + (r0+0)*DD + k);
            float4 t1 = ld4(sT + (r0+1)*DD + k);
            float4 t2 = ld4(sT + (r0+2)*DD + k);
            float4 t3 = ld4(sT + (r0+3)*DD + k);
            float4 f0 = ld4(sFt + (k+0)*FPITCH + c0);
            acc0=fma4(t0.x,f0,acc0); acc1=fma4(t1.x,f0,acc1); acc2=fma4(t2.x,f0,acc2); acc3=fma4(t3.x,f0,acc3);
            float4 f1 = ld4(sFt + (k+1)*FPITCH + c0);
            acc0=fma4(t0.y,f1,acc0); acc1=fma4(t1.y,f1,acc1); acc2=fma4(t2.y,f1,acc2); acc3=fma4(t3.y,f1,acc3);
            float4 f2 = ld4(sFt + (k+2)*FPITCH + c0);
            acc0=fma4(t0.z,f2,acc0); acc1=fma4(t1.z,f2,acc1); acc2=fma4(t2.z,f2,acc2); acc3=fma4(t3.z,f2,acc3);
            float4 f3 = ld4(sFt + (k+3)*FPITCH + c0);
            acc0=fma4(t0.w,f3,acc0); acc1=fma4(t1.w,f3,acc1); acc2=fma4(t2.w,f3,acc2); acc3=fma4(t3.w,f3,acc3);
        }
        float pa[4][3], pb[4][3];
        #pragma unroll
        for (int i=0;i<4;i++)
            #pragma unroll
            for (int r=0;r<3;r++){
                pa[i][r] = g_pnf[(r0+i)*3 + r];
                pb[i][r] = g_pnf[(c0+i)*3 + r];
            }
        float* accp[4] = { &acc0.x, &acc1.x, &acc2.x, &acc3.x };
        #pragma unroll
        for (int i=0;i<4;i++){
            #pragma unroll
            for (int j=0;j<4;j++){
                float q = pa[i][0]*pb[j][0];
                q = fmaf(pa[i][1], pb[j][1], q);
                q = fmaf(pa[i][2], pb[j][2], q);
                accp[i][j] += q;
            }
        }
        if (r0 == c0){
            #pragma unroll
            for (int i=0;i<4;i++) accp[i][i] += expf(g_pnd[r0+i]);
        }
        float* cg = scr_cov + (size_t)b*4096;
        st4(sP + (r0+0)*DD + c0, acc0);  st4(cg + (r0+0)*DD + c0, acc0);
        st4(sP + (r0+1)*DD + c0, acc1);  st4(cg + (r0+1)*DD + c0, acc1);
        st4(sP + (r0+2)*DD + c0, acc2);  st4(cg + (r0+2)*DD + c0, acc2);
        st4(sP + (r0+3)*DD + c0, acc3);  st4(cg + (r0+3)*DD + c0, acc3);
    }
    __syncthreads();

    // HP = Hw @ pred_cov
    {
        const int o0 = ty*2, c0 = tx*4;
        float4 accA = make_float4(0,0,0,0), accB = accA;
        const float* hw0 = g_Hw + (o0+0)*DD;
        const float* hw1 = g_Hw + (o0+1)*DD;
        for (int k=0;k<DD;k+=4){
            float4 h0 = ld4(hw0 + k);
            float4 h1 = ld4(hw1 + k);
            float4 p0 = ld4(sP + (k+0)*DD + c0);
            accA=fma4(h0.x,p0,accA); accB=fma4(h1.x,p0,accB);
            float4 p1 = ld4(sP + (k+1)*DD + c0);
            accA=fma4(h0.y,p1,accA); accB=fma4(h1.y,p1,accB);
            float4 p2 = ld4(sP + (k+2)*DD + c0);
            accA=fma4(h0.z,p2,accA); accB=fma4(h1.z,p2,accB);
            float4 p3 = ld4(sP + (k+3)*DD + c0);
            accA=fma4(h0.w,p3,accA); accB=fma4(h1.w,p3,accB);
        }
        float* hg = scr_hp + (size_t)b*2176;
        st4(sHP + (o0+0)*UPITCH + c0, accA);  st4(hg + (o0+0)*UPITCH + c0, accA);
        st4(sHP + (o0+1)*UPITCH + c0, accB);  st4(hg + (o0+1)*UPITCH + c0, accB);
    }
    __syncthreads();

    // S = HP @ Hw^T + Rn
    {
        const int o0 = ty*2, p0 = tx*2;
        float a00=0.f,a01=0.f,a10=0.f,a11=0.f;
        const float* hw0 = g_Hw + (p0+0)*DD;
        const float* hw1 = g_Hw + (p0+1)*DD;
        for (int k=0;k<DD;k+=4){
            float4 x0 = ld4(sHP + (o0+0)*UPITCH + k);
            float4 x1 = ld4(sHP + (o0+1)*UPITCH + k);
            float4 y0 = ld4(hw0 + k);
            float4 y1 = ld4(hw1 + k);
            a00 = dot4acc(x0,y0,a00); a01 = dot4acc(x0,y1,a01);
            a10 = dot4acc(x1,y0,a10); a11 = dot4acc(x1,y1,a11);
        }
        float oa[2][3], ob[2][3];
        #pragma unroll
        for (int i=0;i<2;i++)
            #pragma unroll
            for (int r=0;r<3;r++){
                oa[i][r] = g_onf[(o0+i)*3 + r];
                ob[i][r] = g_onf[(p0+i)*3 + r];
            }
        a00 += oa[0][0]*ob[0][0] + oa[0][1]*ob[0][1] + oa[0][2]*ob[0][2];
        a01 += oa[0][0]*ob[1][0] + oa[0][1]*ob[1][1] + oa[0][2]*ob[1][2];
        a10 += oa[1][0]*ob[0][0] + oa[1][1]*ob[0][1] + oa[1][2]*ob[0][2];
        a11 += oa[1][0]*ob[1][0] + oa[1][1]*ob[1][1] + oa[1][2]*ob[1][2];
        if (o0 == p0){
            a00 += expf(g_ond[o0+0]);
            a11 += expf(g_ond[o0+1]);
        }
        float* sg = scr_s + (size_t)b*1024;
        sg[(o0+0)*OO + p0+0] = a00;
        sg[(o0+0)*OO + p0+1] = a01;
        sg[(o0+1)*OO + p0+0] = a10;
        sg[(o0+1)*OO + p0+1] = a11;
    }
}

// ========== K2: update (128 threads, 8 CTAs/SM) ==========
#define K2_OFF_S   0
#define K2_OFF_RCP (K2_OFF_S   + OO*SPITCH)
#define K2_OFF_U   (K2_OFF_RCP + 32)
#define K2_OFF_PM  (K2_OFF_U   + OO*UPITCH)
#define K2_OFF_RED (K2_OFF_PM  + DD)
#define K2_FLOATS  (K2_OFF_RED + 4)

__global__ __launch_bounds__(128, 8)
void rkn_update(const float* __restrict__ g_obs,
                const float* __restrict__ g_Hw,
                const float* __restrict__ g_Hb,
                float* __restrict__ o_mean,
                float* __restrict__ o_cov,
                float* __restrict__ o_ll)
{
    extern __shared__ float smem[];
    float* sS   = smem + K2_OFF_S;
    float* sRcp = smem + K2_OFF_RCP;
    float* sU   = smem + K2_OFF_U;
    float* spm  = smem + K2_OFF_PM;
    float* sred = smem + K2_OFF_RED;

    const int b   = blockIdx.x;
    const int tid = threadIdx.x;

    {
        const float* sg = scr_s + (size_t)b*1024;
        for (int i=tid;i<1024;i+=128) sS[(i>>5)*SPITCH + (i&31)] = sg[i];
        const float* hg = scr_hp + (size_t)b*2176;
        for (int i=tid;i<544;i+=128) st4(sU + i*4, ld4(hg + i*4));
        if (tid < DD) spm[tid] = scr_pm[(size_t)b*DD + tid];
    }
    __syncthreads();

    // Cholesky (warp 0) — overlapped with innovation (warp 3)
    if (tid < 32) {
        const int i = tid;
        for (int j=0;j<32;j++){
            float s = 0.f;
            if (i >= j){
                s = sS[i*SPITCH + j];
                for (int k=0;k<j;k++) s = fmaf(-sS[i*SPITCH+k], sS[j*SPITCH+k], s);
            }
            float dj  = __shfl_sync(0xffffffffu, s, j);
            float ljj = sqrtf(dj);
            if (i == j)      sS[i*SPITCH+j] = ljj;
            else if (i > j)  sS[i*SPITCH+j] = s / ljj;
            __syncwarp();
        }
        float di = sS[i*SPITCH+i];
        sRcp[i] = 1.0f / di;
        float ld = logf(di);
        #pragma unroll
        for (int off=16;off;off>>=1) ld += __shfl_xor_sync(0xffffffffu, ld, off);
        if (i == 0) sred[0] = 2.f*ld;
    }
    if (tid >= 96) {   // innovation -> U column 64
        const int o = tid - 96;
        float acc = g_Hb[o];
        const float* hwr = g_Hw + o*DD;
        #pragma unroll 8
        for (int k=0;k<DD;k++) acc = fmaf(hwr[k], spm[k], acc);
        sU[o*UPITCH + 64] = g_obs[b*OO + o] - acc;
    }
    __syncthreads();

    // forward solve in place: columns thread-private
    if (tid < 65) {
        const int c = tid;
        for (int r=0;r<OO;r++){
            float val = sU[r*UPITCH + c];
            for (int k=0;k<r;k++) val = fmaf(-sS[r*SPITCH+k], sU[k*UPITCH + c], val);
            sU[r*UPITCH + c] = val * sRcp[r];
        }
    }
    __syncthreads();

    if (tid == 64) {
        float quad = 0.f;
        #pragma unroll
        for (int o=0;o<OO;o++){ float v = sU[o*UPITCH + 64]; quad = fmaf(v, v, quad); }
        o_ll[b] = -0.5f*(sred[0] + quad + 32.f*LOG2PI);
    }

    if (tid < DD) {   // post_mean = pm + U^T v
        float acc = spm[tid];
        #pragma unroll 8
        for (int o=0;o<OO;o++) acc = fmaf(sU[o*UPITCH + tid], sU[o*UPITCH + 64], acc);
        o_mean[(size_t)b*DD + tid] = acc;
    }

    {   // post_cov = pred_cov - U^T U
        const int tx = tid & 15, ty = tid >> 4;
        const int r0 = ty*8, c0 = tx*4;
        float4 acc[8];
        #pragma unroll
        for (int i=0;i<8;i++) acc[i] = make_float4(0,0,0,0);
        #pragma unroll 4
        for (int o=0;o<OO;o++){
            float4 bv = ld4(sU + o*UPITCH + c0);
            float4 a0 = ld4(sU + o*UPITCH + r0);
            float4 a1 = ld4(sU + o*UPITCH + r0 + 4);
            acc[0]=fma4(a0.x,bv,acc[0]); acc[1]=fma4(a0.y,bv,acc[1]);
            acc[2]=fma4(a0.z,bv,acc[2]); acc[3]=fma4(a0.w,bv,acc[3]);
            acc[4]=fma4(a1.x,bv,acc[4]); acc[5]=fma4(a1.y,bv,acc[5]);
            acc[6]=fma4(a1.z,bv,acc[6]); acc[7]=fma4(a1.w,bv,acc[7]);
        }
        const float* cg = scr_cov + (size_t)b*4096;
        float* outr = o_cov + (size_t)b*4096;
        #pragma unroll
        for (int i=0;i<8;i++){
            float4 pc = ld4(cg + (r0+i)*DD + c0);
            st4(outr + (r0+i)*DD + c0,
                make_float4(pc.x - acc[i].x, pc.y - acc[i].y,
                            pc.z - acc[i].z, pc.w - acc[i].w));
        }
    }
}

extern "C" void kernel_launch(void* const* d_in, const int* in_sizes, int n_in,
                              void* d_out, int out_size)
{
    const float* g_mean  = (const float*)d_in[0];
    const float* g_cov   = (const float*)d_in[1];
    const float* g_obs   = (const float*)d_in[2];
    const float* g_w1    = (const float*)d_in[3];
    const float* g_b1    = (const float*)d_in[4];
    const float* g_w2    = (const float*)d_in[5];
    const float* g_b2    = (const float*)d_in[6];
    const float* g_basis = (const float*)d_in[7];
    const float* g_pnf   = (const float*)d_in[8];
    const float* g_pnd   = (const float*)d_in[9];
    const float* g_onf   = (const float*)d_in[10];
    const float* g_ond   = (const float*)d_in[11];
    const float* g_Hw    = (const float*)d_in[12];
    const float* g_Hb    = (const float*)d_in[13];

    int B = in_sizes[0] / DD;
    if (B > BMAX) B = BMAX;
    float* out    = (float*)d_out;
    float* o_mean = out;
    float* o_cov  = out + (size_t)B*DD;
    float* o_ll   = out + (size_t)B*DD + (size_t)B*DD*DD;

    const int k1_smem = K1_FLOATS * (int)sizeof(float);
    const int k2_smem = K2_FLOATS * (int)sizeof(float);
    cudaFuncSetAttribute(rkn_predict, cudaFuncAttributeMaxDynamicSharedMemorySize, k1_smem);
    cudaFuncSetAttribute(rkn_update,  cudaFuncAttributeMaxDynamicSharedMemorySize, k2_smem);

    rkn_weights<<<B/8, 256>>>(g_mean, g_w1, g_b1, g_w2, g_b2);
    rkn_mixf<<<dim3(B/16, 4), 256>>>(g_basis);
    rkn_predict<<<B, 256, k1_smem>>>(g_mean, g_cov, g_pnf, g_pnd, g_onf, g_ond, g_Hw);
    rkn_update <<<B, 128, k2_smem>>>(g_obs, g_Hw, g_Hb, o_mean, o_cov, o_ll);
}